// round 14
// baseline (speedup 1.0000x reference)
#include <cuda_runtime.h>
#include <math.h>

// ---------------- problem constants ----------------
constexpr int NU = 50000, NF = 50000, NN = 100000;
constexpr int D  = 64,    H2 = 32,    FU = 256;
constexpr int E  = 500000, EP = 500000, EN = 500000;
constexpr int NH = 4;
constexpr float THRESH = 0.3f;

// persistent grids
constexpr int PG_EDGE  = 1184;
constexpr int PG_CONV1 = 740;
constexpr int PG_CONV2 = 1036;
constexpr int PG_TAIL  = 1184;

// ---------------- device scratch ----------------
__device__ float g_u[NU * D];
__device__ float g_f[NF * D];
__device__ float g_x[NN * D];
__device__ float g_y[NN * D];
__device__ float g_maskF[E];
__device__ float g_maskS[E];
__device__ float g_we[E];
__device__ float g_norm[E];
__device__ float g_deg[NN];
__device__ float g_xk[NN * D];
__device__ float g_xk2[NN * D];
__device__ float g_acc[NN * D];
__device__ float g_sums[2];
__device__ int   g_nnz;
__device__ float4 g_nau[NU];
__device__ float4 g_naf[NF];
__device__ int g_cnt2[2 * NN];
__device__ int g_ptr2[2 * NN];
__device__ int g_fill2[2 * NN];
// single-pass scan state
__device__ unsigned long long g_scan_desc[256];
__device__ unsigned int g_scan_ticket;

// ---------------- zero kernels (replace memsets) ----------------
__global__ void zeroA_kernel() {   // sums, nnz, deg
    int i = blockIdx.x * blockDim.x + threadIdx.x;
    if (i < NN) g_deg[i] = 0.f;
    if (i < 2)  g_sums[i] = 0.f;
    if (i == 2) g_nnz = 0;
}

__global__ void zeroB_kernel() {   // cnt2, fill2, scan state
    int i = blockIdx.x * blockDim.x + threadIdx.x;
    if (i < 2 * NN) { g_cnt2[i] = 0; g_fill2[i] = 0; }
    if (i < 256) g_scan_desc[i] = 0ull;
    if (i == 0) g_scan_ticket = 0u;
}

__device__ int g_csrP[EP];
__device__ int g_csrN[EN];

// ---------------- GEMM + fused per-node norms ----------------
__global__ void gemm2(const float* __restrict__ fu, const float* __restrict__ Wu,
                      const float* __restrict__ bu,
                      const float* __restrict__ ff, const float* __restrict__ Wf,
                      const float* __restrict__ bf,
                      const float* __restrict__ mw) {
    constexpr int NBU = (NU + 127) / 128;
    bool isU = blockIdx.x < NBU;
    const float* feat = isU ? fu : ff;
    const float* W    = isU ? Wu : Wf;
    const float* bias = isU ? bu : bf;
    float* out        = isU ? g_u : g_f;
    int rows          = isU ? NU : NF;
    int bx            = isU ? blockIdx.x : blockIdx.x - NBU;

    __shared__ float sA[32][132];
    __shared__ float sB[32][64];
    int tid = threadIdx.x;
    int tx = tid & 15, ty = tid >> 4;
    int row0 = bx * 128;
    float acc[8][4];
#pragma unroll
    for (int i = 0; i < 8; i++)
#pragma unroll
        for (int j = 0; j < 4; j++) acc[i][j] = 0.f;

    for (int k0 = 0; k0 < FU; k0 += 32) {
        int r = tid >> 1;
        int kk = (tid & 1) * 16;
        int grow = row0 + r;
        float4 v[4];
        if (grow < rows) {
            const float4* s = (const float4*)&feat[grow * FU + k0 + kk];
            v[0] = s[0]; v[1] = s[1]; v[2] = s[2]; v[3] = s[3];
        } else {
            v[0] = make_float4(0.f, 0.f, 0.f, 0.f); v[1] = v[0]; v[2] = v[0]; v[3] = v[0];
        }
#pragma unroll
        for (int q = 0; q < 4; q++) {
            sA[kk + q * 4 + 0][r] = v[q].x; sA[kk + q * 4 + 1][r] = v[q].y;
            sA[kk + q * 4 + 2][r] = v[q].z; sA[kk + q * 4 + 3][r] = v[q].w;
        }
        {
            int idx = tid * 8, kw = idx >> 6, cw = idx & 63;
            const float4* ws = (const float4*)&W[(k0 + kw) * D + cw];
            *(float4*)&sB[kw][cw]     = ws[0];
            *(float4*)&sB[kw][cw + 4] = ws[1];
        }
        __syncthreads();
#pragma unroll
        for (int k = 0; k < 32; k++) {
            float4 b  = *(float4*)&sB[k][tx * 4];
            float4 a0 = *(float4*)&sA[k][ty * 8];
            float4 a1 = *(float4*)&sA[k][ty * 8 + 4];
            acc[0][0] += a0.x * b.x; acc[0][1] += a0.x * b.y; acc[0][2] += a0.x * b.z; acc[0][3] += a0.x * b.w;
            acc[1][0] += a0.y * b.x; acc[1][1] += a0.y * b.y; acc[1][2] += a0.y * b.z; acc[1][3] += a0.y * b.w;
            acc[2][0] += a0.z * b.x; acc[2][1] += a0.z * b.y; acc[2][2] += a0.z * b.z; acc[2][3] += a0.z * b.w;
            acc[3][0] += a0.w * b.x; acc[3][1] += a0.w * b.y; acc[3][2] += a0.w * b.z; acc[3][3] += a0.w * b.w;
            acc[4][0] += a1.x * b.x; acc[4][1] += a1.x * b.y; acc[4][2] += a1.x * b.z; acc[4][3] += a1.x * b.w;
            acc[5][0] += a1.y * b.x; acc[5][1] += a1.y * b.y; acc[5][2] += a1.y * b.z; acc[5][3] += a1.y * b.w;
            acc[6][0] += a1.z * b.x; acc[6][1] += a1.z * b.y; acc[6][2] += a1.z * b.z; acc[6][3] += a1.z * b.w;
            acc[7][0] += a1.w * b.x; acc[7][1] += a1.w * b.y; acc[7][2] += a1.w * b.z; acc[7][3] += a1.w * b.w;
        }
        __syncthreads();
    }
    float4 bb = *(const float4*)&bias[tx * 4];
#pragma unroll
    for (int i = 0; i < 8; i++) {
        acc[i][0] = fmaxf(acc[i][0] + bb.x, 0.f);
        acc[i][1] = fmaxf(acc[i][1] + bb.y, 0.f);
        acc[i][2] = fmaxf(acc[i][2] + bb.z, 0.f);
        acc[i][3] = fmaxf(acc[i][3] + bb.w, 0.f);
        int grow = row0 + ty * 8 + i;
        if (grow < rows)
            *(float4*)&out[grow * D + tx * 4] = *(float4*)&acc[i][0];
    }
    // fused per-row per-head norms (16-lane shuffle reduction)
    float mwr[NH][4];
#pragma unroll
    for (int h = 0; h < NH; h++) {
        float4 m4 = *(const float4*)&mw[h * D + tx * 4];
        mwr[h][0] = m4.x; mwr[h][1] = m4.y; mwr[h][2] = m4.z; mwr[h][3] = m4.w;
    }
#pragma unroll
    for (int i = 0; i < 8; i++) {
        float s0 = 0.f, s1 = 0.f, s2 = 0.f, s3 = 0.f;
#pragma unroll
        for (int j = 0; j < 4; j++) {
            float v = acc[i][j];
            float a0 = v * mwr[0][j], a1 = v * mwr[1][j];
            float a2 = v * mwr[2][j], a3 = v * mwr[3][j];
            s0 += a0 * a0; s1 += a1 * a1; s2 += a2 * a2; s3 += a3 * a3;
        }
#pragma unroll
        for (int off = 8; off; off >>= 1) {
            s0 += __shfl_xor_sync(0xffffffffu, s0, off);
            s1 += __shfl_xor_sync(0xffffffffu, s1, off);
            s2 += __shfl_xor_sync(0xffffffffu, s2, off);
            s3 += __shfl_xor_sync(0xffffffffu, s3, off);
        }
        int grow = row0 + ty * 8 + i;
        if (tx == 0 && grow < rows) {
            float4 o = make_float4(fmaxf(sqrtf(s0), 1e-8f), fmaxf(sqrtf(s1), 1e-8f),
                                   fmaxf(sqrtf(s2), 1e-8f), fmaxf(sqrtf(s3), 1e-8f));
            if (isU) g_nau[grow] = o; else g_naf[grow] = o;
        }
    }
}

// ---------------- per-edge cosine similarity (persistent) + |maskF| sum ----------------
__global__ void sim_kernel(const int* __restrict__ e0, const int* __restrict__ e1,
                           const float* __restrict__ mw) {
    __shared__ float smw2[NH * D];
    __shared__ float psum[8];
    if (threadIdx.x < NH * D) { float w = mw[threadIdx.x]; smw2[threadIdx.x] = w * w; }
    __syncthreads();
    int w = threadIdx.x >> 5, lane = threadIdx.x & 31;
    float locsum = 0.f;
    for (int e = blockIdx.x * 8 + w; e < E; e += gridDim.x * 8) {
        int a = e0[e], b = e1[e];
        float u0 = g_u[a * D + lane],  u1 = g_u[a * D + 32 + lane];
        float f0 = g_f[b * D + lane],  f1 = g_f[b * D + 32 + lane];
        float p0 = u0 * f0, p1 = u1 * f1;
        float d[NH];
#pragma unroll
        for (int h = 0; h < NH; h++)
            d[h] = p0 * smw2[h * D + lane] + p1 * smw2[h * D + 32 + lane];
#pragma unroll
        for (int off = 16; off; off >>= 1)
#pragma unroll
            for (int h = 0; h < NH; h++) d[h] += __shfl_xor_sync(0xffffffffu, d[h], off);
        if (lane == 0) {
            float4 na = g_nau[a], nb = g_naf[b];
            float sim = d[0] / (na.x * nb.x) + d[1] / (na.y * nb.y)
                      + d[2] / (na.z * nb.z) + d[3] / (na.w * nb.w);
            sim *= (1.f / NH);
            float m = (sim < THRESH) ? 0.f : sim;
            g_maskF[e] = m;
            locsum += fabsf(m);
        }
    }
    if (lane == 0) psum[w] = locsum;
    __syncthreads();
    if (threadIdx.x == 0) {
        float t = 0.f;
        for (int i = 0; i < 8; i++) t += psum[i];
        if (t != 0.f) atomicAdd(&g_sums[0], t);
    }
}

// ---------------- CSR build ----------------
__global__ void hist_kernel(const int* __restrict__ pd, const int* __restrict__ nd) {
    int i = blockIdx.x * blockDim.x + threadIdx.x;
    if (i < EP) atomicAdd(&g_cnt2[pd[i]], 1);
    else {
        i -= EP;
        if (i < EN) atomicAdd(&g_cnt2[NN + nd[i]], 1);
    }
}

// single-pass decoupled-lookback exclusive scan of g_cnt2 -> g_ptr2
__global__ void scan_kernel() {
    __shared__ int sh[1024];
    __shared__ int sbid;
    __shared__ int sprefix;
    if (threadIdx.x == 0) sbid = atomicAdd(&g_scan_ticket, 1u);
    __syncthreads();
    int bid = sbid;
    int i = bid * 1024 + threadIdx.x;
    int v = (i < 2 * NN) ? g_cnt2[i] : 0;
    sh[threadIdx.x] = v;
    __syncthreads();
    for (int off = 1; off < 1024; off <<= 1) {
        int t = (threadIdx.x >= off) ? sh[threadIdx.x - off] : 0;
        __syncthreads();
        sh[threadIdx.x] += t;
        __syncthreads();
    }
    int incl = sh[threadIdx.x];
    if (threadIdx.x == 0) {
        int total = sh[1023];
        int prefix = 0;
        if (bid == 0) {
            __threadfence();
            atomicExch(&g_scan_desc[0], (2ull << 32) | (unsigned)total);
        } else {
            __threadfence();
            atomicExch(&g_scan_desc[bid], (1ull << 32) | (unsigned)total);
            int j = bid - 1;
            while (true) {
                unsigned long long dsc = atomicAdd(&g_scan_desc[j], 0ull);
                unsigned long long fl = dsc >> 32;
                if (fl == 0ull) continue;
                prefix += (int)(unsigned)dsc;
                if (fl == 2ull) break;
                j--;
            }
            __threadfence();
            atomicExch(&g_scan_desc[bid], (2ull << 32) | (unsigned)(prefix + total));
        }
        sprefix = prefix;
    }
    __syncthreads();
    if (i < 2 * NN) g_ptr2[i] = sprefix + incl - v;
}

__global__ void fill_csr(const int* __restrict__ pe, const int* __restrict__ ne) {
    int i = blockIdx.x * blockDim.x + threadIdx.x;
    if (i < EP) {
        int d = pe[EP + i];
        int slot = atomicAdd(&g_fill2[d], 1);
        g_csrP[g_ptr2[d] + slot] = pe[i];
    } else {
        i -= EP;
        if (i < EN) {
            int d = ne[EN + i];
            int slot = atomicAdd(&g_fill2[NN + d], 1);
            g_csrN[(g_ptr2[NN + d] - EP) + slot] = ne[i];
        }
    }
}

__device__ __forceinline__ float ld_sg(const float* __restrict__ sgu,
                                       const float* __restrict__ sgi, int s, int c) {
    return (s < NU) ? sgu[s * D + c] : sgi[(s - NU) * D + c];
}

// ---------------- fused conv layer 1 (persistent, x4 unrolled gathers) ----------------
__global__ void conv1_fused(const float* __restrict__ sgu, const float* __restrict__ sgi,
                            const float* __restrict__ pl, const float* __restrict__ prw,
                            const float* __restrict__ prb,
                            const float* __restrict__ nl, const float* __restrict__ nrw,
                            const float* __restrict__ nrb) {
    __shared__ float s_pl[D * H2], s_prw[D * H2], s_nl[D * H2], s_nrw[D * H2];
    __shared__ float stage[8 * 192];
    for (int i = threadIdx.x; i < D * H2; i += 256) {
        s_pl[i] = pl[i]; s_prw[i] = prw[i]; s_nl[i] = nl[i]; s_nrw[i] = nrw[i];
    }
    __syncthreads();
    int w = threadIdx.x >> 5, c = threadIdx.x & 31;
    float* st = &stage[w * 192];
    for (int node = blockIdx.x * 8 + w; node < NN; node += gridDim.x * 8) {
        int p0 = g_ptr2[node], p1 = g_ptr2[node + 1];
        int n0 = g_ptr2[NN + node] - EP;
        int n1 = ((node == NN - 1) ? EN : (g_ptr2[NN + node + 1] - EP));
        float mp0 = 0.f, mp1 = 0.f, mn0 = 0.f, mn1 = 0.f;
        int j = p0;
        for (; j + 3 < p1; j += 4) {
            int s0 = g_csrP[j], s1 = g_csrP[j + 1], s2 = g_csrP[j + 2], s3 = g_csrP[j + 3];
            float a0 = ld_sg(sgu, sgi, s0, c), b0 = ld_sg(sgu, sgi, s0, 32 + c);
            float a1 = ld_sg(sgu, sgi, s1, c), b1 = ld_sg(sgu, sgi, s1, 32 + c);
            float a2 = ld_sg(sgu, sgi, s2, c), b2 = ld_sg(sgu, sgi, s2, 32 + c);
            float a3 = ld_sg(sgu, sgi, s3, c), b3 = ld_sg(sgu, sgi, s3, 32 + c);
            mp0 += (a0 + a1) + (a2 + a3); mp1 += (b0 + b1) + (b2 + b3);
        }
        for (; j < p1; j++) {
            int s0 = g_csrP[j];
            mp0 += ld_sg(sgu, sgi, s0, c); mp1 += ld_sg(sgu, sgi, s0, 32 + c);
        }
        j = n0;
        for (; j + 3 < n1; j += 4) {
            int s0 = g_csrN[j], s1 = g_csrN[j + 1], s2 = g_csrN[j + 2], s3 = g_csrN[j + 3];
            float a0 = ld_sg(sgu, sgi, s0, c), b0 = ld_sg(sgu, sgi, s0, 32 + c);
            float a1 = ld_sg(sgu, sgi, s1, c), b1 = ld_sg(sgu, sgi, s1, 32 + c);
            float a2 = ld_sg(sgu, sgi, s2, c), b2 = ld_sg(sgu, sgi, s2, 32 + c);
            float a3 = ld_sg(sgu, sgi, s3, c), b3 = ld_sg(sgu, sgi, s3, 32 + c);
            mn0 += (a0 + a1) + (a2 + a3); mn1 += (b0 + b1) + (b2 + b3);
        }
        for (; j < n1; j++) {
            int s0 = g_csrN[j];
            mn0 += ld_sg(sgu, sgi, s0, c); mn1 += ld_sg(sgu, sgi, s0, 32 + c);
        }
        float invP = 1.f / fmaxf((float)(p1 - p0), 1.f);
        float invN = 1.f / fmaxf((float)(n1 - n0), 1.f);
        st[c]       = mp0 * invP; st[32 + c]  = mp1 * invP;
        st[64 + c]  = mn0 * invN; st[96 + c]  = mn1 * invN;
        st[128 + c] = ld_sg(sgu, sgi, node, c);
        st[160 + c] = ld_sg(sgu, sgi, node, 32 + c);
        __syncwarp();
        float accP = prb[c], accN = nrb[c];
#pragma unroll 8
        for (int k = 0; k < D; k++) {
            float mpk = st[k], mnk = st[64 + k], xk = st[128 + k];
            accP += mpk * s_pl[k * H2 + c] + xk * s_prw[k * H2 + c];
            accN += mnk * s_nl[k * H2 + c] + xk * s_nrw[k * H2 + c];
        }
        g_y[node * D + c]      = fmaxf(accP, 0.f);
        g_y[node * D + 32 + c] = fmaxf(accN, 0.f);
        __syncwarp();
    }
}

// ---------------- fused conv layers 2/3 (persistent, x4 unrolled gathers) ----------------
__global__ void conv2_fused(const float* __restrict__ pl, const float* __restrict__ prw,
                            const float* __restrict__ prb,
                            const float* __restrict__ nl, const float* __restrict__ nrw,
                            const float* __restrict__ nrb,
                            const float* __restrict__ zin, float* __restrict__ zout) {
    __shared__ float s_pl[D * H2], s_nl[D * H2], s_prw[H2 * H2], s_nrw[H2 * H2];
    __shared__ float stage[8 * 192];
    for (int i = threadIdx.x; i < D * H2; i += 256) { s_pl[i] = pl[i]; s_nl[i] = nl[i]; }
    for (int i = threadIdx.x; i < H2 * H2; i += 256) { s_prw[i] = prw[i]; s_nrw[i] = nrw[i]; }
    __syncthreads();
    int w = threadIdx.x >> 5, c = threadIdx.x & 31;
    float* st = &stage[w * 192];
    for (int node = blockIdx.x * 8 + w; node < NN; node += gridDim.x * 8) {
        int p0 = g_ptr2[node], p1 = g_ptr2[node + 1];
        int n0 = g_ptr2[NN + node] - EP;
        int n1 = ((node == NN - 1) ? EN : (g_ptr2[NN + node + 1] - EP));
        float pp = 0.f, pn = 0.f, np_ = 0.f, nn = 0.f;
        int j = p0;
        for (; j + 3 < p1; j += 4) {
            int s0 = g_csrP[j], s1 = g_csrP[j + 1], s2 = g_csrP[j + 2], s3 = g_csrP[j + 3];
            float a0 = zin[s0 * D + c], b0 = zin[s0 * D + 32 + c];
            float a1 = zin[s1 * D + c], b1 = zin[s1 * D + 32 + c];
            float a2 = zin[s2 * D + c], b2 = zin[s2 * D + 32 + c];
            float a3 = zin[s3 * D + c], b3 = zin[s3 * D + 32 + c];
            pp += (a0 + a1) + (a2 + a3); pn += (b0 + b1) + (b2 + b3);
        }
        for (; j < p1; j++) {
            int s0 = g_csrP[j];
            pp += zin[s0 * D + c]; pn += zin[s0 * D + 32 + c];
        }
        j = n0;
        for (; j + 3 < n1; j += 4) {
            int s0 = g_csrN[j], s1 = g_csrN[j + 1], s2 = g_csrN[j + 2], s3 = g_csrN[j + 3];
            float a0 = zin[s0 * D + c], b0 = zin[s0 * D + 32 + c];
            float a1 = zin[s1 * D + c], b1 = zin[s1 * D + 32 + c];
            float a2 = zin[s2 * D + c], b2 = zin[s2 * D + 32 + c];
            float a3 = zin[s3 * D + c], b3 = zin[s3 * D + 32 + c];
            np_ += (a0 + a1) + (a2 + a3); nn += (b0 + b1) + (b2 + b3);
        }
        for (; j < n1; j++) {
            int s0 = g_csrN[j];
            np_ += zin[s0 * D + c]; nn += zin[s0 * D + 32 + c];
        }
        float invP = 1.f / fmaxf((float)(p1 - p0), 1.f);
        float invN = 1.f / fmaxf((float)(n1 - n0), 1.f);
        st[c]       = pp * invP;  st[32 + c] = nn * invN;
        st[64 + c]  = pn * invP;  st[96 + c] = np_ * invN;
        st[128 + c] = zin[node * D + c];
        st[160 + c] = zin[node * D + 32 + c];
        __syncwarp();
        float accP = prb[c], accN = nrb[c];
#pragma unroll 8
        for (int k = 0; k < D; k++) {
            accP += st[k]      * s_pl[k * H2 + c];
            accN += st[64 + k] * s_nl[k * H2 + c];
        }
#pragma unroll 8
        for (int k = 0; k < H2; k++) {
            accP += st[128 + k] * s_prw[k * H2 + c];
            accN += st[160 + k] * s_nrw[k * H2 + c];
        }
        zout[node * D + c]      = fmaxf(accP, 0.f);
        zout[node * D + 32 + c] = fmaxf(accN, 0.f);
        __syncwarp();
    }
}

// ---------------- per-edge classifier (persistent) + |maskS| sum ----------------
__global__ void class_kernel(const int* __restrict__ e0, const int* __restrict__ e1,
                             const float* __restrict__ z,
                             const float* __restrict__ lw, const float* __restrict__ lb) {
    __shared__ float slw[2 * D * 3];
    __shared__ float slb[3];
    __shared__ float psum[8];
    for (int i = threadIdx.x; i < 2 * D * 3; i += 256) slw[i] = lw[i];
    if (threadIdx.x < 3) slb[threadIdx.x] = lb[threadIdx.x];
    __syncthreads();
    int w = threadIdx.x >> 5, lane = threadIdx.x & 31;
    float locsum = 0.f;
    for (int e = blockIdx.x * 8 + w; e < E; e += gridDim.x * 8) {
        int a = e0[e], b = e1[e];
        float za0 = z[a * D + lane], za1 = z[a * D + 32 + lane];
        float zb0 = z[b * D + lane], zb1 = z[b * D + 32 + lane];
        float v0 = za0 * slw[lane * 3 + 0] + za1 * slw[(32 + lane) * 3 + 0]
                 + zb0 * slw[(64 + lane) * 3 + 0] + zb1 * slw[(96 + lane) * 3 + 0];
        float v1 = za0 * slw[lane * 3 + 1] + za1 * slw[(32 + lane) * 3 + 1]
                 + zb0 * slw[(64 + lane) * 3 + 1] + zb1 * slw[(96 + lane) * 3 + 1];
        float v2 = za0 * slw[lane * 3 + 2] + za1 * slw[(32 + lane) * 3 + 2]
                 + zb0 * slw[(64 + lane) * 3 + 2] + zb1 * slw[(96 + lane) * 3 + 2];
#pragma unroll
        for (int off = 16; off; off >>= 1) {
            v0 += __shfl_xor_sync(0xffffffffu, v0, off);
            v1 += __shfl_xor_sync(0xffffffffu, v1, off);
            v2 += __shfl_xor_sync(0xffffffffu, v2, off);
        }
        if (lane == 0) {
            v0 += slb[0]; v1 += slb[1]; v2 += slb[2];
            int cls = 0; float best = v0;
            if (v1 > best) { best = v1; cls = 1; }
            if (v2 > best) { cls = 2; }
            float m = (float)(cls - 1);
            g_maskS[e] = m;
            locsum += fabsf(m);
        }
    }
    if (lane == 0) psum[w] = locsum;
    __syncthreads();
    if (threadIdx.x == 0) {
        float t = 0.f;
        for (int i = 0; i < 8; i++) t += psum[i];
        if (t != 0.f) atomicAdd(&g_sums[1], t);
    }
}

// ---------------- mask fusion ----------------
__global__ void wedge_kernel(const int* __restrict__ e0, const float* __restrict__ fw) {
    int i = blockIdx.x * blockDim.x + threadIdx.x;
    if (i >= E) return;
    float w0 = fw[0], w1 = fw[1], w2 = fw[2];
    float m = fmaxf(w0, fmaxf(w1, w2));
    float ex0 = expf(w0 - m), ex1 = expf(w1 - m), ex2 = expf(w2 - m);
    float s = ex0 + ex1 + ex2;
    float sw0 = ex0 / s, sw1 = ex1 / s, sw2 = ex2 / s;
    float nO = 1.f / (float)E;
    float nF = g_maskF[i] / fmaxf(g_sums[0], 1e-12f);
    float nS = g_maskS[i] / fmaxf(g_sums[1], 1e-12f);
    float fused = sw0 * nO + sw1 * nF + sw2 * nS;
    float w = (fused > 0.5f) ? 1.f : 0.f;
    g_we[i] = w;
    if (w != 0.f) atomicAdd(&g_deg[e0[i]], w);
    unsigned msk = __ballot_sync(__activemask(), w != 0.f);
    if ((threadIdx.x & 31) == 0 && msk) atomicAdd(&g_nnz, __popc(msk));
}

__global__ void norm_kernel(const int* __restrict__ e0, const int* __restrict__ e1) {
    int i = blockIdx.x * blockDim.x + threadIdx.x;
    if (i >= E) return;
    float w = g_we[i];
    if (w == 0.f) { g_norm[i] = 0.f; return; }
    float d0 = g_deg[e0[i]], d1 = g_deg[e1[i]];
    float r0 = (d0 > 0.f) ? rsqrtf(fmaxf(d0, 1e-12f)) : 0.f;
    float r1 = (d1 > 0.f) ? rsqrtf(fmaxf(d1, 1e-12f)) : 0.f;
    g_norm[i] = r0 * w * r1;
}

// ---------------- LightGCN ----------------
__global__ void initacc_out(const float* __restrict__ lgu, const float* __restrict__ lgi,
                            float* __restrict__ out) {
    int i = blockIdx.x * blockDim.x + threadIdx.x;
    if (i >= NN * D) return;
    constexpr int A = NU * D;
    float v;
    if (i < A) { v = lgu[i];     out[A + i]     = v; }
    else       { v = lgi[i - A]; out[2 * A + i] = v; }
    g_acc[i] = v;
    g_xk[i]  = v;
    g_xk2[i] = 0.f;
}

__device__ __forceinline__ void red_add_v4(float* p, float x, float y, float z, float w) {
    asm volatile("red.global.add.v4.f32 [%0], {%1,%2,%3,%4};"
                 :: "l"(p), "f"(x), "f"(y), "f"(z), "f"(w) : "memory");
}

__global__ void prop_kernel(const int* __restrict__ e0, const int* __restrict__ e1,
                            const float* __restrict__ xin, float* __restrict__ xout) {
    if (g_nnz == 0) return;
    for (long long t = (long long)blockIdx.x * blockDim.x + threadIdx.x;
         t < (long long)E * 16; t += (long long)gridDim.x * blockDim.x) {
        int e = (int)(t >> 4);
        float nm = g_norm[e];
        if (nm == 0.f) continue;
        int c = ((int)t & 15) * 4;
        int s = e1[e], d = e0[e];
        float4 v = *(const float4*)&xin[s * D + c];
        red_add_v4(&xout[d * D + c], nm * v.x, nm * v.y, nm * v.z, nm * v.w);
    }
}

__global__ void accadd_zero(const float* __restrict__ xnew, float* __restrict__ xold) {
    if (g_nnz == 0) return;
    for (int i = blockIdx.x * blockDim.x + threadIdx.x; i < NN * D;
         i += gridDim.x * blockDim.x) {
        g_acc[i] += xnew[i];
        xold[i] = 0.f;
    }
}

__global__ void out_final(const float* __restrict__ x3, float* __restrict__ out) {
    int i = blockIdx.x * blockDim.x + threadIdx.x;
    if (i >= NN * D) return;
    constexpr int A = NU * D;
    float v = (g_acc[i] + x3[i]) * 0.25f;
    if (i < A) out[i]     = v;
    else       out[A + i] = v;
}

// ---------------- launch ----------------
extern "C" void kernel_launch(void* const* d_in, const int* in_sizes, int n_in,
                              void* d_out, int out_size) {
    const float* user_feat = (const float*)d_in[0];
    const float* food_feat = (const float*)d_in[1];
    const int*   ei        = (const int*)d_in[2];
    const int*   pe        = (const int*)d_in[3];
    const int*   ne        = (const int*)d_in[4];
    const float* W_user    = (const float*)d_in[5];
    const float* b_user    = (const float*)d_in[6];
    const float* W_food    = (const float*)d_in[7];
    const float* b_food    = (const float*)d_in[8];
    const float* metric_w  = (const float*)d_in[9];
    const float* fusion_w  = (const float*)d_in[10];
    const float* sg_u      = (const float*)d_in[11];
    const float* sg_i      = (const float*)d_in[12];
    const float* c1_pl     = (const float*)d_in[13];
    const float* c1_prw    = (const float*)d_in[14];
    const float* c1_prb    = (const float*)d_in[15];
    const float* c1_nl     = (const float*)d_in[16];
    const float* c1_nrw    = (const float*)d_in[17];
    const float* c1_nrb    = (const float*)d_in[18];
    const float* cs_pl     = (const float*)d_in[19];
    const float* cs_prw    = (const float*)d_in[20];
    const float* cs_prb    = (const float*)d_in[21];
    const float* cs_nl     = (const float*)d_in[22];
    const float* cs_nrw    = (const float*)d_in[23];
    const float* cs_nrb    = (const float*)d_in[24];
    const float* lin_w     = (const float*)d_in[25];
    const float* lin_b     = (const float*)d_in[26];
    const float* lg_u      = (const float*)d_in[27];
    const float* lg_i      = (const float*)d_in[28];
    float* out = (float*)d_out;

    void *a_x, *a_y, *a_xk, *a_xk2;
    cudaGetSymbolAddress(&a_x, g_x);
    cudaGetSymbolAddress(&a_y, g_y);
    cudaGetSymbolAddress(&a_xk, g_xk);
    cudaGetSymbolAddress(&a_xk2, g_xk2);

    static cudaStream_t sB = 0, sC = 0;
    static cudaEvent_t evR = 0, evB = 0, evC = 0;
    static bool s_init = false;
    if (!s_init) {
        cudaStreamCreateWithFlags(&sB, cudaStreamNonBlocking);
        cudaStreamCreateWithFlags(&sC, cudaStreamNonBlocking);
        cudaEventCreateWithFlags(&evR, cudaEventDisableTiming);
        cudaEventCreateWithFlags(&evB, cudaEventDisableTiming);
        cudaEventCreateWithFlags(&evC, cudaEventDisableTiming);
        s_init = true;
    }

    const int TPB = 256;
    const int gE     = (E + TPB - 1) / TPB;
    const int gBE    = (EP + EN + TPB - 1) / TPB;
    const int gND    = (NN * D + TPB - 1) / TPB;
    const int nScanBlocks = (2 * NN + 1023) / 1024;
    constexpr int NBU = (NU + 127) / 128;

    // zero cross-chain accumulators before the fork
    zeroA_kernel<<<(NN + TPB - 1) / TPB, TPB>>>();

    // fork
    cudaEventRecord(evR, 0);
    if (sB) cudaStreamWaitEvent(sB, evR, 0);
    if (sC) cudaStreamWaitEvent(sC, evR, 0);

    // ---- chain B (sB): CSR -> conv x3 -> class(+|maskS| sum) ----
    zeroB_kernel<<<(2 * NN + TPB - 1) / TPB, TPB, 0, sB>>>();
    hist_kernel<<<gBE, TPB, 0, sB>>>(pe + EP, ne + EN);
    scan_kernel<<<nScanBlocks, 1024, 0, sB>>>();
    fill_csr<<<gBE, TPB, 0, sB>>>(pe, ne);
    conv1_fused<<<PG_CONV1, TPB, 0, sB>>>(sg_u, sg_i,
                                          c1_pl, c1_prw, c1_prb, c1_nl, c1_nrw, c1_nrb);
    conv2_fused<<<PG_CONV2, TPB, 0, sB>>>(cs_pl, cs_prw, cs_prb, cs_nl, cs_nrw, cs_nrb,
                                          (const float*)a_y, (float*)a_x);
    conv2_fused<<<PG_CONV2, TPB, 0, sB>>>(cs_pl + D * H2, cs_prw + H2 * H2, cs_prb + H2,
                                          cs_nl + D * H2, cs_nrw + H2 * H2, cs_nrb + H2,
                                          (const float*)a_x, (float*)a_y);
    class_kernel<<<PG_EDGE, TPB, 0, sB>>>(ei, ei + E, (const float*)a_y, lin_w, lin_b);
    cudaEventRecord(evB, sB);

    // ---- chain C (sC): LightGCN init + lg output copies ----
    initacc_out<<<gND, TPB, 0, sC>>>(lg_u, lg_i, out);
    cudaEventRecord(evC, sC);

    // ---- chain A (origin): GEMM(+norms) -> sim(+|maskF| sum) ----
    gemm2<<<2 * NBU, 256>>>(user_feat, W_user, b_user, food_feat, W_food, b_food, metric_w);
    sim_kernel<<<PG_EDGE, TPB>>>(ei, ei + E, metric_w);

    // join
    cudaStreamWaitEvent(0, evB, 0);
    cudaStreamWaitEvent(0, evC, 0);

    // ---- tail ----
    wedge_kernel<<<gE, TPB>>>(ei, fusion_w);
    norm_kernel<<<gE, TPB>>>(ei, ei + E);

    prop_kernel<<<PG_TAIL, TPB>>>(ei, ei + E, (const float*)a_xk, (float*)a_xk2);
    accadd_zero<<<PG_TAIL, TPB>>>((const float*)a_xk2, (float*)a_xk);
    prop_kernel<<<PG_TAIL, TPB>>>(ei, ei + E, (const float*)a_xk2, (float*)a_xk);
    accadd_zero<<<PG_TAIL, TPB>>>((const float*)a_xk, (float*)a_xk2);
    prop_kernel<<<PG_TAIL, TPB>>>(ei, ei + E, (const float*)a_xk, (float*)a_xk2);
    out_final<<<gND, TPB>>>((const float*)a_xk2, out);
}